// round 6
// baseline (speedup 1.0000x reference)
#include <cuda_runtime.h>

#define NB 8
#define NN 256
#define ND 128
#define NH 256
#define NK 128

typedef unsigned long long u64t;

// ---------------- scratch ----------------------------------------------------
__device__ float g_hi[NB*NN*NH];      // hi + b1 folded in   (2 MB)
__device__ float g_hj[NB*NN*NH];      // hj                  (2 MB)

// ---------------- packed f32x2 helpers ---------------------------------------
__device__ __forceinline__ u64t add2(u64t a, u64t b) {
    u64t r; asm("add.rn.f32x2 %0, %1, %2;" : "=l"(r) : "l"(a), "l"(b)); return r;
}
__device__ __forceinline__ u64t fma2(u64t a, u64t b, u64t c) {
    u64t r; asm("fma.rn.f32x2 %0, %1, %2, %3;" : "=l"(r) : "l"(a), "l"(b), "l"(c)); return r;
}
__device__ __forceinline__ u64t relu2(u64t a) {
    float lo, hi;
    asm("mov.b64 {%0,%1}, %2;" : "=f"(lo), "=f"(hi) : "l"(a));
    lo = fmaxf(lo, 0.f); hi = fmaxf(hi, 0.f);
    u64t r; asm("mov.b64 %0, {%1,%2};" : "=l"(r) : "f"(lo), "f"(hi)); return r;
}
__device__ __forceinline__ float hsum2(u64t a) {
    float lo, hi;
    asm("mov.b64 {%0,%1}, %2;" : "=f"(lo), "=f"(hi) : "l"(a));
    return lo + hi;
}
__device__ __forceinline__ float ex2a(float v) {
    float y;
    asm("ex2.approx.f32 %0, %1;" : "=f"(y) : "f"(v));
    return y;
}

// ---------------- Kernel A: [2048x128] @ [128x512] with smem-staged W1 -------
__global__ __launch_bounds__(128) void k_embed(const float* __restrict__ ae,
                                               const float* __restrict__ W1,
                                               const float* __restrict__ b1) {
    __shared__ float sa[32][129];
    __shared__ float wseg[64][64];

    int row0  = blockIdx.x * 32;
    int hcol0 = blockIdx.y * 64;
    bool isb  = hcol0 >= 256;
    int gcol  = hcol0 & 255;
    int tid   = threadIdx.x;
    int hq    = tid & 15;
    int rg    = tid >> 4;

    #pragma unroll
    for (int s = 0; s < 8; s++) {
        int idx = s*128 + tid;
        int r = idx >> 5, q = idx & 31;
        float4 v = *(const float4*)&ae[(size_t)(row0 + r)*ND + q*4];
        sa[r][q*4+0] = v.x; sa[r][q*4+1] = v.y;
        sa[r][q*4+2] = v.z; sa[r][q*4+3] = v.w;
    }

    float4 bb = isb ? make_float4(0.f,0.f,0.f,0.f)
                    : *(const float4*)&b1[gcol + hq*4];
    float4 acc0 = bb, acc1 = bb, acc2 = bb, acc3 = bb;

    const float* wbase = W1 + (size_t)(isb ? 128 : 0)*NH + gcol;

    #pragma unroll
    for (int kc = 0; kc < 128; kc += 64) {
        __syncthreads();
        #pragma unroll
        for (int s = 0; s < 8; s++) {
            int idx = s*128 + tid;
            int kk = idx >> 4, q = idx & 15;
            *(float4*)&wseg[kk][q*4] =
                *(const float4*)&wbase[(size_t)(kc + kk)*NH + q*4];
        }
        __syncthreads();

        #pragma unroll 4
        for (int kk = 0; kk < 64; kk++) {
            float4 w = *(const float4*)&wseg[kk][hq*4];
            float a0 = sa[rg*4+0][kc+kk];
            float a1 = sa[rg*4+1][kc+kk];
            float a2 = sa[rg*4+2][kc+kk];
            float a3 = sa[rg*4+3][kc+kk];
            acc0.x = fmaf(a0,w.x,acc0.x); acc0.y = fmaf(a0,w.y,acc0.y);
            acc0.z = fmaf(a0,w.z,acc0.z); acc0.w = fmaf(a0,w.w,acc0.w);
            acc1.x = fmaf(a1,w.x,acc1.x); acc1.y = fmaf(a1,w.y,acc1.y);
            acc1.z = fmaf(a1,w.z,acc1.z); acc1.w = fmaf(a1,w.w,acc1.w);
            acc2.x = fmaf(a2,w.x,acc2.x); acc2.y = fmaf(a2,w.y,acc2.y);
            acc2.z = fmaf(a2,w.z,acc2.z); acc2.w = fmaf(a2,w.w,acc2.w);
            acc3.x = fmaf(a3,w.x,acc3.x); acc3.y = fmaf(a3,w.y,acc3.y);
            acc3.z = fmaf(a3,w.z,acc3.z); acc3.w = fmaf(a3,w.w,acc3.w);
        }
    }

    float* dst = isb ? g_hj : g_hi;
    int c = (isb ? hcol0 - 256 : hcol0) + hq*4;
    int r0 = row0 + rg*4;
    *(float4*)&dst[(size_t)(r0+0)*NH + c] = acc0;
    *(float4*)&dst[(size_t)(r0+1)*NH + c] = acc1;
    *(float4*)&dst[(size_t)(r0+2)*NH + c] = acc2;
    *(float4*)&dst[(size_t)(r0+3)*NH + c] = acc3;
}

// ---------------- Kernel B: pipelined pair-MLP + RBF -------------------------
// Block: 128 threads, TWO 32(i) x 8(j) tiles (j0, j0+8). Phase-2 (RBF+store)
// of tile 0 is interleaved into the phase-1 h-loop of tile 1, mixing
// FMA / MUFU / STG pipes within every warp.
#define TI 32
#define TJ 8
#define HCH 128
#define PADW 132

// 2-pair packed step: i rows (tii, tii+16), single j row
#define PSTEP2(A0,A1,C0,W0,W1v) {                                        \
    u64t r0 = relu2(add2((A0), (C0)));                                    \
    u64t r1 = relu2(add2((A1), (C0)));                                    \
    acc0a = fma2(r0, (W0), acc0a); acc0b = fma2(r0, (W1v), acc0b);        \
    acc1a = fma2(r1, (W0), acc1a); acc1b = fma2(r1, (W1v), acc1b); }

#define RBF_ELEM(M,X,BV,OP) {                                            \
    float v = fmaf((M), (X), (BV));                                       \
    float e0 = ex2a(fmaf(fmaf(nA0, v, pB0), v, qC0));                     \
    float e1 = ex2a(fmaf(fmaf(nA1, v, pB1), v, qC1));                     \
    float e2 = ex2a(fmaf(fmaf(nA2, v, pB2), v, qC2));                     \
    float e3 = ex2a(fmaf(fmaf(nA3, v, pB3), v, qC3));                     \
    __stcs((float4*)(OP), make_float4(e0, e1, e2, e3)); }

__global__ __launch_bounds__(128, 7) void k_fused(
        const float* __restrict__ x,
        const float* __restrict__ W2,
        const float* __restrict__ b2,
        const float* __restrict__ means,
        const float* __restrict__ temps,
        float* __restrict__ out) {
    __shared__ float shi[TI*PADW];         // 16.9 KB
    __shared__ float shj[TJ*PADW];         // 4.2 KB
    __shared__ float sw0[NH];              // 1 KB
    __shared__ float sw1[NH];              // 1 KB
    // double buffer: [par][ sx(256) | smul(256) | sbias(256) ]
    __shared__ float sbuf[2][768];         // 6 KB

    int b   = blockIdx.z;
    int i0  = blockIdx.y * TI;
    int j00 = blockIdx.x * (2*TJ);
    int tid  = threadIdx.x;                // 0..127
    int lane = tid & 31;
    int wid  = tid >> 5;                   // 0..3

    int tii = tid >> 3;                    // 0..15 -> i rows tii, tii+16
    int tjj = tid & 7;                     // j row

    // per-lane RBF constants: arg = n*v^2 + p*v + q
    const float L2E = 1.4426950408889634f;
    int k0 = lane * 4;
    float4 mm4 = *(const float4*)&means[k0];
    float4 tt4 = *(const float4*)&temps[k0];
    float nA0 = -fabsf(tt4.x)*L2E, nA1 = -fabsf(tt4.y)*L2E;
    float nA2 = -fabsf(tt4.z)*L2E, nA3 = -fabsf(tt4.w)*L2E;
    float pB0 = -2.f*nA0*mm4.x, pB1 = -2.f*nA1*mm4.y;
    float pB2 = -2.f*nA2*mm4.z, pB3 = -2.f*nA3*mm4.w;
    float qC0 = nA0*mm4.x*mm4.x, qC1 = nA1*mm4.y*mm4.y;
    float qC2 = nA2*mm4.z*mm4.z, qC3 = nA3*mm4.w*mm4.w;

    const float s = 0.0625f;               // 1/sqrt(2*128)
    float cb0 = __ldg(&b2[0]) * s;
    float cb1 = __ldg(&b2[1]) * s;

    // W2 columns to smem
    #pragma unroll
    for (int h = tid; h < NH; h += 128) {
        sw0[h] = W2[2*h];
        sw1[h] = W2[2*h + 1];
    }

    const float* hi_base = g_hi + (size_t)(b*NN + i0)*NH;

    size_t obase0 = ((size_t)(b*NN + i0)*NN + j00) * NK + k0;       // tile 0
    size_t obase1 = obase0 + (size_t)TJ * NK;                        // tile 1

    #pragma unroll
    for (int t = 0; t < 2; t++) {
        int j0 = j00 + t*TJ;
        const float* hj_base = g_hj + (size_t)(b*NN + j0)*NH;

        // x tile -> sbuf[t][0..255]  (32 rows x 8 cols)
        if (tid < 64) {
            int r = tid >> 1, c = tid & 1;
            *(float4*)&sbuf[t][r*8 + c*4] =
                *(const float4*)&x[(size_t)(b*NN + i0 + r)*NN + j0 + c*4];
        }

        u64t acc0a=0ull, acc0b=0ull, acc1a=0ull, acc1b=0ull;

        #pragma unroll
        for (int ch = 0; ch < 2; ch++) {
            __syncthreads();               // prior shi/shj readers + buf writers done
            // stage shi 32x128 (1024 f4) + shj 8x128 (256 f4): 10 f4/thread
            #pragma unroll
            for (int s5 = 0; s5 < 10; s5++) {
                int idx = s5*128 + tid;
                if (idx < 1024) {
                    int r = idx >> 5, c = idx & 31;
                    *(float4*)&shi[r*PADW + c*4] =
                        *(const float4*)&hi_base[(size_t)r*NH + ch*HCH + c*4];
                } else {
                    int id2 = idx - 1024;
                    int r = id2 >> 5, c = id2 & 31;
                    *(float4*)&shj[r*PADW + c*4] =
                        *(const float4*)&hj_base[(size_t)r*NH + ch*HCH + c*4];
                }
            }
            __syncthreads();

            const float* wp0 = sw0 + ch*HCH;
            const float* wp1 = sw1 + ch*HCH;

            // 8 groups: 4 h4-steps of phase-1(tile t) + 4 RBF iters of tile 0
            #pragma unroll 1
            for (int g8 = 0; g8 < 8; g8++) {
                #pragma unroll
                for (int u = 0; u < 4; u++) {
                    int h4 = g8*4 + u;
                    ulonglong2 A0 = *(const ulonglong2*)&shi[(tii   )*PADW + h4*4];
                    ulonglong2 A1 = *(const ulonglong2*)&shi[(tii+16)*PADW + h4*4];
                    ulonglong2 C0 = *(const ulonglong2*)&shj[(tjj   )*PADW + h4*4];
                    ulonglong2 W0 = *(const ulonglong2*)&wp0[h4*4];
                    ulonglong2 W1v= *(const ulonglong2*)&wp1[h4*4];
                    PSTEP2(A0.x, A1.x, C0.x, W0.x, W1v.x);
                    PSTEP2(A0.y, A1.y, C0.y, W0.y, W1v.y);
                }
                if (t == 1) {
                    // consume tile 0: 4 pairs per group, warp owns 64 pairs
                    #pragma unroll
                    for (int u2 = 0; u2 < 4; u2++) {
                        int pp = ch*32 + g8*4 + u2;        // 0..63
                        int p  = wid*64 + pp;              // 0..255
                        float mv = sbuf[0][256 + p];
                        float bv = sbuf[0][512 + p];
                        float xv = sbuf[0][p];
                        int i_loc = p >> 3, j_loc = p & 7;
                        RBF_ELEM(mv, xv, bv,
                                 out + obase0 + ((size_t)i_loc*NN + j_loc)*NK);
                    }
                }
            }
        }

        // write mul/bias for tile t (own slots; ordered by next sync)
        {
            int p0 = tii*8 + tjj;
            sbuf[t][256 + p0      ] = fmaf(hsum2(acc0a), s, cb0);
            sbuf[t][512 + p0      ] = fmaf(hsum2(acc0b), s, cb1);
            sbuf[t][256 + p0 + 128] = fmaf(hsum2(acc1a), s, cb0);
            sbuf[t][512 + p0 + 128] = fmaf(hsum2(acc1b), s, cb1);
        }
    }

    __syncthreads();                       // tile-1 mul/bias visible

    // epilogue: RBF + store for tile 1
    #pragma unroll 4
    for (int pp = 0; pp < 64; pp++) {
        int p = wid*64 + pp;
        float mv = sbuf[1][256 + p];
        float bv = sbuf[1][512 + p];
        float xv = sbuf[1][p];
        int i_loc = p >> 3, j_loc = p & 7;
        RBF_ELEM(mv, xv, bv, out + obase1 + ((size_t)i_loc*NN + j_loc)*NK);
    }
}

// ---------------- launch ------------------------------------------------------
extern "C" void kernel_launch(void* const* d_in, const int* in_sizes, int n_in,
                              void* d_out, int out_size) {
    const float* x     = (const float*)d_in[0];   // (B,N,N)
    const float* ae    = (const float*)d_in[1];   // (B,N,D)
    const float* W1    = (const float*)d_in[2];   // (2D,H)
    const float* b1    = (const float*)d_in[3];   // (H)
    const float* W2    = (const float*)d_in[4];   // (H,2)
    const float* b2    = (const float*)d_in[5];   // (2)
    const float* means = (const float*)d_in[6];   // (K)
    const float* temps = (const float*)d_in[7];   // (K)
    float* out = (float*)d_out;                   // (B,N,N,K)

    dim3 gA(NB*NN/32, 8);                         // 512 blocks
    k_embed<<<gA, 128>>>(ae, W1, b1);

    dim3 gB(NN/(2*TJ), NN/TI, NB);                // (16, 8, 8) = 1024 blocks
    k_fused<<<gB, 128>>>(x, W2, b2, means, temps, out);
}